// round 13
// baseline (speedup 1.0000x reference)
#include <cuda_runtime.h>

#define NPTS   8192
#define BATCH  8
#define S_ALL  512
#define K_ATTN 128
#define K_NONE 384
#define DF     64

typedef unsigned long long ull;

// packed f32x2 helpers (lane-wise IEEE fp32 — bit-identical to scalar fmaf)
#define PACK2(d, s)      asm("mov.b64 %0, {%1, %1};" : "=l"(d) : "f"(s))
#define UNPACK2(lo, hi, s) asm("mov.b64 {%0, %1}, %2;" : "=f"(lo), "=f"(hi) : "l"(s))
#define FMA2(d, a, b, c) asm("fma.rn.f32x2 %0, %1, %2, %3;" : "=l"(d) : "l"(a), "l"(b), "l"(c))

// ---------------- scratch (static device arrays; no allocation) ----------------
__device__ float g_pts_t[BATCH * NPTS * DF];      // points transposed to [B][N][64]
__device__ float g_new_xyz[BATCH * S_ALL * 3];    // sampled (masked) coords [B][S][3]
// transposed weights: row = input channel, col = output (adjacent outputs contiguous)
__device__ float g_w0t[68 * 64];                  // [ch(pad 68)][64 out]
__device__ float g_w1t[64 * 64];                  // [ch][64 out]
__device__ float g_w2t[64 * 128];                 // [ch][128 out]
// FPS chunk-persist state (none branch only)
__device__ float g_cx[BATCH][8193];
__device__ float g_cy[BATCH][8193];
__device__ float g_cz[BATCH][8193];
__device__ int   g_cid[BATCH][8193];
__device__ float g_cmd[BATCH][8448];              // per-slot min-dist
__device__ int   g_state[BATCH][4];               // m, rep, cur

// ---------------- prep: transpose weights to [ch][out] ----------------
__global__ void prep_w_kernel(const float* __restrict__ w0,
                              const float* __restrict__ w1,
                              const float* __restrict__ w2) {
    int i = blockIdx.x * 256 + threadIdx.x;
    if (i < 68 * 64) {                       // g_w0t[c][o] = w0[o][c], pad c>=67 with 0
        int c = i >> 6, o = i & 63;
        g_w0t[i] = (c < 67) ? w0[o * 67 + c] : 0.0f;
    }
    if (i < 64 * 64) {                       // g_w1t[c][o] = w1[o][c]
        int c = i >> 6, o = i & 63;
        g_w1t[i] = w1[o * 64 + c];
    }
    if (i < 64 * 128) {                      // g_w2t[c][o] = w2[o][c]
        int c = i >> 7, o = i & 127;
        g_w2t[i] = w2[o * 64 + c];
    }
}

// ---------------- transpose points [B,64,N] -> [B,N,64] ----------------
__global__ void transpose_kernel(const float* __restrict__ points) {
    __shared__ float tile[32][33];
    int b  = blockIdx.z;
    int c0 = blockIdx.y * 32;
    int n0 = blockIdx.x * 32;
    int tx = threadIdx.x, ty = threadIdx.y;
    tile[ty][tx] = points[(b * DF + c0 + ty) * NPTS + n0 + tx];
    __syncthreads();
    g_pts_t[(b * NPTS + n0 + ty) * DF + c0 + tx] = tile[tx][ty];
}

// ---------------- FPS with origin-duplicate compression, chunked [k0,k1) ----------------
template <int BRANCH>
__global__ __launch_bounds__(1024) void fps_kernel(
    const float* __restrict__ xyz, const float* __restrict__ attention,
    float* __restrict__ out, int k0, int k1)
{
    extern __shared__ float dsm[];
    float* sx  = dsm;                    // [8193]
    float* sy  = sx + 8193;
    float* sz  = sy + 8193;
    int*   sid = (int*)(sz + 8193);      // [8193]
    float* smd = (float*)(sid + 8193);   // [4097] overflow min-dist

    __shared__ unsigned sscan[32];
    __shared__ unsigned long long sred[2][32];
    __shared__ int srep;

    int b = blockIdx.x;
    const int K     = BRANCH ? K_NONE : K_ATTN;
    const int s_off = BRANCH ? K_ATTN : 0;
    int t = threadIdx.x;
    int wid = t >> 5, lane = t & 31;

    const float* xb = xyz + (size_t)b * 3 * NPTS;
    const float* ab = attention + (size_t)b * NPTS;

    int m, rep, cur;
    float px[4], py[4], pz[4], md[4];

    if (k0 == 0) {
        if (t == 0) srep = 0x7FFFFFFF;

        int n0 = t * 8;
        float X[8], Y[8], Z[8], W[8];
        {
            const float4* p = (const float4*)(xb + n0);
            float4 v0 = p[0], v1 = p[1];
            X[0]=v0.x; X[1]=v0.y; X[2]=v0.z; X[3]=v0.w; X[4]=v1.x; X[5]=v1.y; X[6]=v1.z; X[7]=v1.w;
            p = (const float4*)(xb + NPTS + n0);
            v0 = p[0]; v1 = p[1];
            Y[0]=v0.x; Y[1]=v0.y; Y[2]=v0.z; Y[3]=v0.w; Y[4]=v1.x; Y[5]=v1.y; Y[6]=v1.z; Y[7]=v1.w;
            p = (const float4*)(xb + 2 * NPTS + n0);
            v0 = p[0]; v1 = p[1];
            Z[0]=v0.x; Z[1]=v0.y; Z[2]=v0.z; Z[3]=v0.w; Z[4]=v1.x; Z[5]=v1.y; Z[6]=v1.z; Z[7]=v1.w;
            p = (const float4*)(ab + n0);
            v0 = p[0]; v1 = p[1];
            W[0]=v0.x; W[1]=v0.y; W[2]=v0.z; W[3]=v0.w; W[4]=v1.x; W[5]=v1.y; W[6]=v1.z; W[7]=v1.w;
        }
        int myrep = 0x7FFFFFFF;
        #pragma unroll
        for (int j = 0; j < 8; j++) {
            float a = W[j];
            float w = BRANCH ? __fsub_rn(1.0f, a) : a;   // exact: a in {0,1}
            W[j] = w;
            X[j] = __fmul_rn(w, X[j]);
            Y[j] = __fmul_rn(w, Y[j]);
            Z[j] = __fmul_rn(w, Z[j]);
            if (w == 0.0f && (n0 + j) < myrep) myrep = n0 + j;
        }
        __syncthreads();
        if (myrep != 0x7FFFFFFF) atomicMin(&srep, myrep);
        __syncthreads();
        rep = srep;

        unsigned cnt = 0, kmask = 0;
        #pragma unroll
        for (int j = 0; j < 8; j++) {
            bool kp = (W[j] != 0.0f) || ((n0 + j) == rep);
            if (kp) { kmask |= (1u << j); cnt++; }
        }
        unsigned inc = cnt;
        #pragma unroll
        for (int off = 1; off < 32; off <<= 1) {
            unsigned v = __shfl_up_sync(0xffffffffu, inc, off);
            if (lane >= off) inc += v;
        }
        if (lane == 31) sscan[wid] = inc;
        __syncthreads();
        if (wid == 0) {
            unsigned v = sscan[lane];
            #pragma unroll
            for (int off = 1; off < 32; off <<= 1) {
                unsigned u = __shfl_up_sync(0xffffffffu, v, off);
                if (lane >= off) v += u;
            }
            sscan[lane] = v;
        }
        __syncthreads();
        m = (int)sscan[31];
        int o = (int)((wid ? sscan[wid - 1] : 0u) + (inc - cnt));
        #pragma unroll
        for (int j = 0; j < 8; j++) {
            if ((kmask >> j) & 1u) {
                sx[o] = X[j]; sy[o] = Y[j]; sz[o] = Z[j]; sid[o] = n0 + j;
                o++;
            }
        }
        for (int s2 = t; s2 < 4097; s2 += 1024) smd[s2] = 1e10f;
        __syncthreads();

        #pragma unroll
        for (int j = 0; j < 4; j++) {
            int sl = t + j * 1024;
            bool v = sl < m;
            px[j] = v ? sx[sl] : 0.0f;
            py[j] = v ? sy[sl] : 0.0f;
            pz[j] = v ? sz[sl] : 0.0f;
            md[j] = v ? 1e10f : 0.0f;
        }
        cur = 0;

        if (k1 < K) {
            for (int sl = t; sl < m; sl += 1024) {
                g_cx[b][sl] = sx[sl]; g_cy[b][sl] = sy[sl];
                g_cz[b][sl] = sz[sl]; g_cid[b][sl] = sid[sl];
            }
            if (t == 0) { g_state[b][0] = m; g_state[b][1] = rep; }
        }
    } else {
        m   = g_state[b][0];
        rep = g_state[b][1];
        cur = g_state[b][2];
        for (int sl = t; sl < m; sl += 1024) {
            sx[sl] = g_cx[b][sl]; sy[sl] = g_cy[b][sl];
            sz[sl] = g_cz[b][sl]; sid[sl] = g_cid[b][sl];
        }
        #pragma unroll
        for (int j = 0; j < 4; j++) md[j] = g_cmd[b][t + j * 1024];
        for (int sl = 4096 + t; sl < m; sl += 1024) smd[sl - 4096] = g_cmd[b][sl];
        __syncthreads();
        #pragma unroll
        for (int j = 0; j < 4; j++) {
            int sl = t + j * 1024;
            px[j] = 0.0f; py[j] = 0.0f; pz[j] = 0.0f;
            if (sl < m) { px[j] = sx[sl]; py[j] = sy[sl]; pz[j] = sz[sl]; }
        }
    }

    float* out_xyz  = out;                                           // [B,3,512]
    float* out_attn = out + BATCH * 3 * S_ALL + BATCH * 128 * S_ALL; // [B,1,512]

    for (int k = k0; k < k1; k++) {
        float bx = sx[cur], by = sy[cur], bz = sz[cur];
        if (t == 0) {
            int s = s_off + k;
            out_xyz[(b * 3 + 0) * S_ALL + s] = bx;
            out_xyz[(b * 3 + 1) * S_ALL + s] = by;
            out_xyz[(b * 3 + 2) * S_ALL + s] = bz;
            g_new_xyz[(b * S_ALL + s) * 3 + 0] = bx;
            g_new_xyz[(b * S_ALL + s) * 3 + 1] = by;
            g_new_xyz[(b * S_ALL + s) * 3 + 2] = bz;
            int orig = sid[cur];
            float att = BRANCH ? ((orig == rep) ? 1.0f : 0.0f)
                               : ((orig == rep) ? 0.0f : 1.0f);
            out_attn[b * S_ALL + s] = att;
        }
        if (k == K - 1) break;

        unsigned long long bk = 0ull;
        #pragma unroll
        for (int j = 0; j < 4; j++) {
            float dx = __fsub_rn(px[j], bx);
            float dy = __fsub_rn(py[j], by);
            float dz = __fsub_rn(pz[j], bz);
            float d2 = __fadd_rn(__fadd_rn(__fmul_rn(dx, dx), __fmul_rn(dy, dy)),
                                 __fmul_rn(dz, dz));
            float mn = fminf(md[j], d2);
            md[j] = mn;
            int sl = t + j * 1024;
            unsigned long long key =
                ((unsigned long long)__float_as_uint(mn) << 32) |
                (unsigned long long)(0xFFFFFFFFu - (unsigned)sl);
            if (key > bk) bk = key;
        }
        for (int sl = 4096 + t; sl < m; sl += 1024) {
            float dx = __fsub_rn(sx[sl], bx);
            float dy = __fsub_rn(sy[sl], by);
            float dz = __fsub_rn(sz[sl], bz);
            float d2 = __fadd_rn(__fadd_rn(__fmul_rn(dx, dx), __fmul_rn(dy, dy)),
                                 __fmul_rn(dz, dz));
            float mn = fminf(smd[sl - 4096], d2);
            smd[sl - 4096] = mn;
            unsigned long long key =
                ((unsigned long long)__float_as_uint(mn) << 32) |
                (unsigned long long)(0xFFFFFFFFu - (unsigned)sl);
            if (key > bk) bk = key;
        }
        unsigned vb   = (unsigned)(bk >> 32);
        unsigned vmax = __reduce_max_sync(0xffffffffu, vb);
        unsigned lo   = (vb == vmax) ? (unsigned)bk : 0u;
        unsigned lmax = __reduce_max_sync(0xffffffffu, lo);
        if (lane == 0) sred[k & 1][wid] = ((unsigned long long)vmax << 32) | lmax;
        __syncthreads();
        unsigned long long e = sred[k & 1][lane];
        vb   = (unsigned)(e >> 32);
        vmax = __reduce_max_sync(0xffffffffu, vb);
        lo   = (vb == vmax) ? (unsigned)e : 0u;
        lmax = __reduce_max_sync(0xffffffffu, lo);
        cur  = (int)(0xFFFFFFFFu - lmax);
    }

    if (k1 < K) {
        #pragma unroll
        for (int j = 0; j < 4; j++) g_cmd[b][t + j * 1024] = md[j];
        for (int sl = 4096 + t; sl < m; sl += 1024) g_cmd[b][sl] = smd[sl - 4096];
        if (t == 0) g_state[b][2] = cur;
    }
}

// ================= group + MLP + maxpool: 128-thread CTA per (b,s) =================
// One-shot global reads use __ldcs (evict-first) so the 65KB of weights stay
// L1-resident for the __ldg hits; channel loops unroll-limited for I$ fit.
template <int S_BASE, int NS>
__global__ __launch_bounds__(128, 8) void group_mlp_kernel(
    const float* __restrict__ xyz,
    const float* __restrict__ b0, const float* __restrict__ b1,
    const float* __restrict__ b2,
    float* __restrict__ out)
{
    __shared__ __align__(16) float sfeat[68 * 64];   // [c][k]; rows 0..63 reused for h1, h2
    __shared__ int sidx[64];
    __shared__ int swarp[8];                         // [0..3]=first half, [4..7]=second half

    int t = threadIdx.x;
    int wid = t >> 5, lane = t & 31;
    unsigned lmaskb = (1u << lane) - 1u;

    int bs = blockIdx.x;
    int b = bs / NS;
    int s = S_BASE + (bs - b * NS);

    const float* xb = xyz + (size_t)b * 3 * NPTS;
    float qx = g_new_xyz[(b * S_ALL + s) * 3 + 0];
    float qy = g_new_xyz[(b * S_ALL + s) * 3 + 1];
    float qz = g_new_xyz[(b * S_ALL + s) * 3 + 2];
    const float R2 = (float)(0.4 * 0.4);

    if (t < 64) { sidx[t] = -1; sfeat[67 * 64 + t] = 0.0f; }
    __syncthreads();

    // ---- ball query: ordered first-64 collection, 256-point rounds ----
    int total = 0;
    for (int mm = 0; mm < 32; mm++) {
        int n0 = mm * 256 + t;
        int n1 = n0 + 128;
        float x0 = __ldcs(&xb[n0]), y0 = __ldcs(&xb[NPTS + n0]), z0 = __ldcs(&xb[2 * NPTS + n0]);
        float x1 = __ldcs(&xb[n1]), y1 = __ldcs(&xb[NPTS + n1]), z1 = __ldcs(&xb[2 * NPTS + n1]);
        float dx0 = __fsub_rn(qx, x0);
        float dy0 = __fsub_rn(qy, y0);
        float dz0 = __fsub_rn(qz, z0);
        float d20 = __fadd_rn(__fadd_rn(__fmul_rn(dx0, dx0), __fmul_rn(dy0, dy0)),
                              __fmul_rn(dz0, dz0));
        float dx1 = __fsub_rn(qx, x1);
        float dy1 = __fsub_rn(qy, y1);
        float dz1 = __fsub_rn(qz, z1);
        float d21 = __fadd_rn(__fadd_rn(__fmul_rn(dx1, dx1), __fmul_rn(dy1, dy1)),
                              __fmul_rn(dz1, dz1));
        bool p0 = d20 < R2;
        bool p1 = d21 < R2;
        unsigned ball0 = __ballot_sync(0xffffffffu, p0);
        unsigned ball1 = __ballot_sync(0xffffffffu, p1);
        if (lane == 0) { swarp[wid] = __popc(ball0); swarp[4 + wid] = __popc(ball1); }
        __syncthreads();
        int sum0 = 0, off0 = total, off1 = 0;
        #pragma unroll
        for (int w = 0; w < 4; w++) {
            int v0 = swarp[w];
            sum0 += v0;
            if (w < wid) off0 += v0;
        }
        int sum1 = 0;
        off1 = total + sum0;
        #pragma unroll
        for (int w = 0; w < 4; w++) {
            int v1 = swarp[4 + w];
            sum1 += v1;
            if (w < wid) off1 += v1;
        }
        if (p0) {
            int slot = off0 + __popc(ball0 & lmaskb);
            if (slot < 64) sidx[slot] = n0;
        }
        if (p1) {
            int slot = off1 + __popc(ball1 & lmaskb);
            if (slot < 64) sidx[slot] = n1;
        }
        total += sum0 + sum1;
        __syncthreads();
        if (total >= 64) break;
    }

    // ---- feat [68][64] ----
    if (t < 64) {
        int idx = sidx[t];
        float gx = (idx >= 0) ? __ldcs(&xb[idx]) : 0.0f;
        float gy = (idx >= 0) ? __ldcs(&xb[NPTS + idx]) : 0.0f;
        float gz = (idx >= 0) ? __ldcs(&xb[2 * NPTS + idx]) : 0.0f;
        sfeat[0 * 64 + t] = __fsub_rn(gx, qx);
        sfeat[1 * 64 + t] = __fsub_rn(gy, qy);
        sfeat[2 * 64 + t] = __fsub_rn(gz, qz);
    }
    {
        int kk = t & 63, fq = t >> 6;            // 2 threads per sample row, 8 float4 each
        int idx = sidx[kk];
        int gi = (idx >= 0) ? idx : (NPTS - 1);
        const float4* row = (const float4*)(g_pts_t + ((size_t)b * NPTS + gi) * DF);
        #pragma unroll
        for (int f2 = 0; f2 < 8; f2++) {
            int f = fq * 8 + f2;
            float4 v = __ldcs(&row[f]);
            sfeat[(3 + 4 * f + 0) * 64 + kk] = v.x;
            sfeat[(3 + 4 * f + 1) * 64 + kk] = v.y;
            sfeat[(3 + 4 * f + 2) * 64 + kk] = v.z;
            sfeat[(3 + 4 * f + 3) * 64 + kk] = v.w;
        }
    }
    __syncthreads();

    int og = t >> 4;              // 0..7  (8 output rows each -> 4 output PAIRS)
    int kb = (t & 15) * 4;        // 0..60 (4 samples)
    const float* fp = sfeat + kb;

    ull acc[4][4];                // [output pair][sample]

    // ---- layer1: 68(pad) -> 64, relu ----
    {
        const float* w0p = g_w0t + og * 8;    // column offset; row stride 64
        #pragma unroll
        for (int p = 0; p < 4; p++) {
            ull bv = __ldg((const ull*)(b0 + og * 8 + 2 * p));
            acc[p][0] = bv; acc[p][1] = bv; acc[p][2] = bv; acc[p][3] = bv;
        }
        #pragma unroll 4
        for (int c = 0; c < 68; c++) {
            float4 f = *(const float4*)(fp + c * 64);
            ull fb0, fb1, fb2, fb3;
            PACK2(fb0, f.x); PACK2(fb1, f.y); PACK2(fb2, f.z); PACK2(fb3, f.w);
            ulonglong2 wA = __ldg((const ulonglong2*)(w0p + c * 64));      // pairs (o0,o1),(o2,o3)
            ulonglong2 wB = __ldg((const ulonglong2*)(w0p + c * 64 + 4));  // pairs (o4,o5),(o6,o7)
            FMA2(acc[0][0], wA.x, fb0, acc[0][0]); FMA2(acc[0][1], wA.x, fb1, acc[0][1]);
            FMA2(acc[0][2], wA.x, fb2, acc[0][2]); FMA2(acc[0][3], wA.x, fb3, acc[0][3]);
            FMA2(acc[1][0], wA.y, fb0, acc[1][0]); FMA2(acc[1][1], wA.y, fb1, acc[1][1]);
            FMA2(acc[1][2], wA.y, fb2, acc[1][2]); FMA2(acc[1][3], wA.y, fb3, acc[1][3]);
            FMA2(acc[2][0], wB.x, fb0, acc[2][0]); FMA2(acc[2][1], wB.x, fb1, acc[2][1]);
            FMA2(acc[2][2], wB.x, fb2, acc[2][2]); FMA2(acc[2][3], wB.x, fb3, acc[2][3]);
            FMA2(acc[3][0], wB.y, fb0, acc[3][0]); FMA2(acc[3][1], wB.y, fb1, acc[3][1]);
            FMA2(acc[3][2], wB.y, fb2, acc[3][2]); FMA2(acc[3][3], wB.y, fb3, acc[3][3]);
        }
        __syncthreads();   // all layer-1 reads of sfeat complete
        #pragma unroll
        for (int p = 0; p < 4; p++) {
            float e0, o0, e1, o1, e2, o2, e3, o3;
            UNPACK2(e0, o0, acc[p][0]); UNPACK2(e1, o1, acc[p][1]);
            UNPACK2(e2, o2, acc[p][2]); UNPACK2(e3, o3, acc[p][3]);
            float4 re = { fmaxf(e0,0.f), fmaxf(e1,0.f), fmaxf(e2,0.f), fmaxf(e3,0.f) };
            float4 ro = { fmaxf(o0,0.f), fmaxf(o1,0.f), fmaxf(o2,0.f), fmaxf(o3,0.f) };
            *(float4*)(sfeat + (og * 8 + 2 * p + 0) * 64 + kb) = re;
            *(float4*)(sfeat + (og * 8 + 2 * p + 1) * 64 + kb) = ro;
        }
    }
    __syncthreads();

    // ---- layer2: 64 -> 64, relu ----
    {
        const float* w1p = g_w1t + og * 8;
        #pragma unroll
        for (int p = 0; p < 4; p++) {
            ull bv = __ldg((const ull*)(b1 + og * 8 + 2 * p));
            acc[p][0] = bv; acc[p][1] = bv; acc[p][2] = bv; acc[p][3] = bv;
        }
        #pragma unroll 4
        for (int c = 0; c < 64; c++) {
            float4 f = *(const float4*)(fp + c * 64);
            ull fb0, fb1, fb2, fb3;
            PACK2(fb0, f.x); PACK2(fb1, f.y); PACK2(fb2, f.z); PACK2(fb3, f.w);
            ulonglong2 wA = __ldg((const ulonglong2*)(w1p + c * 64));
            ulonglong2 wB = __ldg((const ulonglong2*)(w1p + c * 64 + 4));
            FMA2(acc[0][0], wA.x, fb0, acc[0][0]); FMA2(acc[0][1], wA.x, fb1, acc[0][1]);
            FMA2(acc[0][2], wA.x, fb2, acc[0][2]); FMA2(acc[0][3], wA.x, fb3, acc[0][3]);
            FMA2(acc[1][0], wA.y, fb0, acc[1][0]); FMA2(acc[1][1], wA.y, fb1, acc[1][1]);
            FMA2(acc[1][2], wA.y, fb2, acc[1][2]); FMA2(acc[1][3], wA.y, fb3, acc[1][3]);
            FMA2(acc[2][0], wB.x, fb0, acc[2][0]); FMA2(acc[2][1], wB.x, fb1, acc[2][1]);
            FMA2(acc[2][2], wB.x, fb2, acc[2][2]); FMA2(acc[2][3], wB.x, fb3, acc[2][3]);
            FMA2(acc[3][0], wB.y, fb0, acc[3][0]); FMA2(acc[3][1], wB.y, fb1, acc[3][1]);
            FMA2(acc[3][2], wB.y, fb2, acc[3][2]); FMA2(acc[3][3], wB.y, fb3, acc[3][3]);
        }
        __syncthreads();   // all layer-2 reads complete before overwrite
        #pragma unroll
        for (int p = 0; p < 4; p++) {
            float e0, o0, e1, o1, e2, o2, e3, o3;
            UNPACK2(e0, o0, acc[p][0]); UNPACK2(e1, o1, acc[p][1]);
            UNPACK2(e2, o2, acc[p][2]); UNPACK2(e3, o3, acc[p][3]);
            float4 re = { fmaxf(e0,0.f), fmaxf(e1,0.f), fmaxf(e2,0.f), fmaxf(e3,0.f) };
            float4 ro = { fmaxf(o0,0.f), fmaxf(o1,0.f), fmaxf(o2,0.f), fmaxf(o3,0.f) };
            *(float4*)(sfeat + (og * 8 + 2 * p + 0) * 64 + kb) = re;
            *(float4*)(sfeat + (og * 8 + 2 * p + 1) * 64 + kb) = ro;
        }
    }
    __syncthreads();

    // ---- layer3: 64 -> 128, relu + maxpool; two passes of 64 outputs ----
    {
        float* out_points = out + BATCH * 3 * S_ALL;   // [B,128,512]
        #pragma unroll 1
        for (int h = 0; h < 2; h++) {
            const float* w2p = g_w2t + h * 64 + og * 8;   // row stride 128
            #pragma unroll
            for (int p = 0; p < 4; p++) {
                ull bv = __ldg((const ull*)(b2 + h * 64 + og * 8 + 2 * p));
                acc[p][0] = bv; acc[p][1] = bv; acc[p][2] = bv; acc[p][3] = bv;
            }
            #pragma unroll 4
            for (int c = 0; c < 64; c++) {
                float4 f = *(const float4*)(fp + c * 64);
                ull fb0, fb1, fb2, fb3;
                PACK2(fb0, f.x); PACK2(fb1, f.y); PACK2(fb2, f.z); PACK2(fb3, f.w);
                ulonglong2 wA = __ldg((const ulonglong2*)(w2p + c * 128));
                ulonglong2 wB = __ldg((const ulonglong2*)(w2p + c * 128 + 4));
                FMA2(acc[0][0], wA.x, fb0, acc[0][0]); FMA2(acc[0][1], wA.x, fb1, acc[0][1]);
                FMA2(acc[0][2], wA.x, fb2, acc[0][2]); FMA2(acc[0][3], wA.x, fb3, acc[0][3]);
                FMA2(acc[1][0], wA.y, fb0, acc[1][0]); FMA2(acc[1][1], wA.y, fb1, acc[1][1]);
                FMA2(acc[1][2], wA.y, fb2, acc[1][2]); FMA2(acc[1][3], wA.y, fb3, acc[1][3]);
                FMA2(acc[2][0], wB.x, fb0, acc[2][0]); FMA2(acc[2][1], wB.x, fb1, acc[2][1]);
                FMA2(acc[2][2], wB.x, fb2, acc[2][2]); FMA2(acc[2][3], wB.x, fb3, acc[2][3]);
                FMA2(acc[3][0], wB.y, fb0, acc[3][0]); FMA2(acc[3][1], wB.y, fb1, acc[3][1]);
                FMA2(acc[3][2], wB.y, fb2, acc[3][2]); FMA2(acc[3][3], wB.y, fb3, acc[3][3]);
            }
            #pragma unroll
            for (int p = 0; p < 4; p++) {
                float e0, o0, e1, o1, e2, o2, e3, o3;
                UNPACK2(e0, o0, acc[p][0]); UNPACK2(e1, o1, acc[p][1]);
                UNPACK2(e2, o2, acc[p][2]); UNPACK2(e3, o3, acc[p][3]);
                float me = fmaxf(fmaxf(e0, e1), fmaxf(e2, e3));
                float mo = fmaxf(fmaxf(o0, o1), fmaxf(o2, o3));
                #pragma unroll
                for (int off = 1; off < 16; off <<= 1) {
                    me = fmaxf(me, __shfl_xor_sync(0xffffffffu, me, off));
                    mo = fmaxf(mo, __shfl_xor_sync(0xffffffffu, mo, off));
                }
                if ((t & 15) == 0) {
                    size_t base = (size_t)b * 128 + h * 64 + og * 8 + 2 * p;
                    out_points[(base + 0) * S_ALL + s] = fmaxf(me, 0.0f);
                    out_points[(base + 1) * S_ALL + s] = fmaxf(mo, 0.0f);
                }
            }
        }
    }
}

extern "C" void kernel_launch(void* const* d_in, const int* in_sizes, int n_in,
                              void* d_out, int out_size) {
    const float* xyz       = (const float*)d_in[0];
    const float* points    = (const float*)d_in[1];
    const float* attention = (const float*)d_in[2];
    const float* w0 = (const float*)d_in[3];
    const float* b0 = (const float*)d_in[4];
    const float* w1 = (const float*)d_in[5];
    const float* b1 = (const float*)d_in[6];
    const float* w2 = (const float*)d_in[7];
    const float* b2 = (const float*)d_in[8];
    float* out = (float*)d_out;

    static cudaStream_t sA = nullptr, sB = nullptr, sD = nullptr;
    static cudaEvent_t eFork = nullptr, eT = nullptr, eA = nullptr, eD = nullptr;
    static cudaEvent_t eN[4] = {nullptr, nullptr, nullptr, nullptr};
    if (sA == nullptr) {
        cudaStreamCreateWithFlags(&sA, cudaStreamNonBlocking);
        cudaStreamCreateWithFlags(&sB, cudaStreamNonBlocking);
        cudaStreamCreateWithFlags(&sD, cudaStreamNonBlocking);
        cudaEventCreateWithFlags(&eFork, cudaEventDisableTiming);
        cudaEventCreateWithFlags(&eT,    cudaEventDisableTiming);
        cudaEventCreateWithFlags(&eA,    cudaEventDisableTiming);
        cudaEventCreateWithFlags(&eD,    cudaEventDisableTiming);
        for (int i = 0; i < 4; i++) cudaEventCreateWithFlags(&eN[i], cudaEventDisableTiming);
    }

    const int fps_smem = 8193 * 16 + 4097 * 4;
    cudaFuncSetAttribute(fps_kernel<0>, cudaFuncAttributeMaxDynamicSharedMemorySize, fps_smem);
    cudaFuncSetAttribute(fps_kernel<1>, cudaFuncAttributeMaxDynamicSharedMemorySize, fps_smem);

    prep_w_kernel<<<32, 256>>>(w0, w1, w2);   // 8192 threads cover 64*128

    cudaEventRecord(eFork, 0);
    cudaStreamWaitEvent(sA, eFork, 0);
    cudaStreamWaitEvent(sB, eFork, 0);
    cudaStreamWaitEvent(sD, eFork, 0);

    // stream A: transpose -> FPS(attn) -> group(attn sites 0..127)
    transpose_kernel<<<dim3(256, 2, 8), dim3(32, 32), 0, sA>>>(points);
    cudaEventRecord(eT, sA);
    fps_kernel<0><<<BATCH, 1024, fps_smem, sA>>>(xyz, attention, out, 0, K_ATTN);
    group_mlp_kernel<0, 128><<<BATCH * 128, 128, 0, sA>>>(xyz, b0, b1, b2, out);
    cudaEventRecord(eA, sA);

    // stream B: FPS(none) in 4 chunks of 96 iterations
    fps_kernel<1><<<BATCH, 1024, fps_smem, sB>>>(xyz, attention, out, 0, 96);
    cudaEventRecord(eN[0], sB);
    fps_kernel<1><<<BATCH, 1024, fps_smem, sB>>>(xyz, attention, out, 96, 192);
    cudaEventRecord(eN[1], sB);
    fps_kernel<1><<<BATCH, 1024, fps_smem, sB>>>(xyz, attention, out, 192, 288);
    cudaEventRecord(eN[2], sB);
    fps_kernel<1><<<BATCH, 1024, fps_smem, sB>>>(xyz, attention, out, 288, 384);
    cudaEventRecord(eN[3], sB);

    // stream D: group(none) in 4 site-chunks, gated on FPS chunks (+transpose)
    cudaStreamWaitEvent(sD, eT, 0);
    cudaStreamWaitEvent(sD, eN[0], 0);
    group_mlp_kernel<128, 96><<<BATCH * 96, 128, 0, sD>>>(xyz, b0, b1, b2, out);
    cudaStreamWaitEvent(sD, eN[1], 0);
    group_mlp_kernel<224, 96><<<BATCH * 96, 128, 0, sD>>>(xyz, b0, b1, b2, out);
    cudaStreamWaitEvent(sD, eN[2], 0);
    group_mlp_kernel<320, 96><<<BATCH * 96, 128, 0, sD>>>(xyz, b0, b1, b2, out);
    cudaStreamWaitEvent(sD, eN[3], 0);
    group_mlp_kernel<416, 96><<<BATCH * 96, 128, 0, sD>>>(xyz, b0, b1, b2, out);
    cudaEventRecord(eD, sD);

    cudaStreamWaitEvent(0, eA, 0);
    cudaStreamWaitEvent(0, eD, 0);
}

// round 14
// speedup vs baseline: 1.1964x; 1.1964x over previous
#include <cuda_runtime.h>

#define NPTS   8192
#define BATCH  8
#define S_ALL  512
#define K_ATTN 128
#define K_NONE 384
#define DF     64

typedef unsigned long long ull;

// packed f32x2 helpers (lane-wise IEEE fp32 — bit-identical to scalar fmaf)
#define PACK2(d, s)      asm("mov.b64 %0, {%1, %1};" : "=l"(d) : "f"(s))
#define UNPACK2(lo, hi, s) asm("mov.b64 {%0, %1}, %2;" : "=f"(lo), "=f"(hi) : "l"(s))
#define FMA2(d, a, b, c) asm("fma.rn.f32x2 %0, %1, %2, %3;" : "=l"(d) : "l"(a), "l"(b), "l"(c))

// ---------------- scratch (static device arrays; no allocation) ----------------
__device__ float g_pts_t[BATCH * NPTS * DF];      // points transposed to [B][N][64]
__device__ float g_new_xyz[BATCH * S_ALL * 3];    // sampled (masked) coords [B][S][3]
// transposed weights: row = input channel, col = output (adjacent outputs contiguous)
__device__ float g_w0t[68 * 64];                  // [ch(pad 68)][64 out]
__device__ float g_w1t[64 * 64];                  // [ch][64 out]
__device__ float g_w2t[64 * 128];                 // [ch][128 out]
// FPS chunk-persist state (none branch only)
__device__ float g_cx[BATCH][8193];
__device__ float g_cy[BATCH][8193];
__device__ float g_cz[BATCH][8193];
__device__ int   g_cid[BATCH][8193];
__device__ float g_cmd[BATCH][8448];              // per-slot min-dist
__device__ int   g_state[BATCH][4];               // m, rep, cur

// ---------------- prep: transpose weights to [ch][out] ----------------
__global__ void prep_w_kernel(const float* __restrict__ w0,
                              const float* __restrict__ w1,
                              const float* __restrict__ w2) {
    int i = blockIdx.x * 256 + threadIdx.x;
    if (i < 68 * 64) {                       // g_w0t[c][o] = w0[o][c], pad c>=67 with 0
        int c = i >> 6, o = i & 63;
        g_w0t[i] = (c < 67) ? w0[o * 67 + c] : 0.0f;
    }
    if (i < 64 * 64) {                       // g_w1t[c][o] = w1[o][c]
        int c = i >> 6, o = i & 63;
        g_w1t[i] = w1[o * 64 + c];
    }
    if (i < 64 * 128) {                      // g_w2t[c][o] = w2[o][c]
        int c = i >> 7, o = i & 127;
        g_w2t[i] = w2[o * 64 + c];
    }
}

// ---------------- transpose points [B,64,N] -> [B,N,64] ----------------
__global__ void transpose_kernel(const float* __restrict__ points) {
    __shared__ float tile[32][33];
    int b  = blockIdx.z;
    int c0 = blockIdx.y * 32;
    int n0 = blockIdx.x * 32;
    int tx = threadIdx.x, ty = threadIdx.y;
    tile[ty][tx] = points[(b * DF + c0 + ty) * NPTS + n0 + tx];
    __syncthreads();
    g_pts_t[(b * NPTS + n0 + ty) * DF + c0 + tx] = tile[tx][ty];
}

// ---------------- FPS with origin-duplicate compression, chunked [k0,k1) ----------------
template <int BRANCH>
__global__ __launch_bounds__(1024) void fps_kernel(
    const float* __restrict__ xyz, const float* __restrict__ attention,
    float* __restrict__ out, int k0, int k1)
{
    extern __shared__ float dsm[];
    float* sx  = dsm;                    // [8193]
    float* sy  = sx + 8193;
    float* sz  = sy + 8193;
    int*   sid = (int*)(sz + 8193);      // [8193]
    float* smd = (float*)(sid + 8193);   // [4097] overflow min-dist

    __shared__ unsigned sscan[32];
    __shared__ unsigned long long sred[2][32];
    __shared__ int srep;

    int b = blockIdx.x;
    const int K     = BRANCH ? K_NONE : K_ATTN;
    const int s_off = BRANCH ? K_ATTN : 0;
    int t = threadIdx.x;
    int wid = t >> 5, lane = t & 31;

    const float* xb = xyz + (size_t)b * 3 * NPTS;
    const float* ab = attention + (size_t)b * NPTS;

    int m, rep, cur;
    float px[4], py[4], pz[4], md[4];

    if (k0 == 0) {
        if (t == 0) srep = 0x7FFFFFFF;

        int n0 = t * 8;
        float X[8], Y[8], Z[8], W[8];
        {
            const float4* p = (const float4*)(xb + n0);
            float4 v0 = p[0], v1 = p[1];
            X[0]=v0.x; X[1]=v0.y; X[2]=v0.z; X[3]=v0.w; X[4]=v1.x; X[5]=v1.y; X[6]=v1.z; X[7]=v1.w;
            p = (const float4*)(xb + NPTS + n0);
            v0 = p[0]; v1 = p[1];
            Y[0]=v0.x; Y[1]=v0.y; Y[2]=v0.z; Y[3]=v0.w; Y[4]=v1.x; Y[5]=v1.y; Y[6]=v1.z; Y[7]=v1.w;
            p = (const float4*)(xb + 2 * NPTS + n0);
            v0 = p[0]; v1 = p[1];
            Z[0]=v0.x; Z[1]=v0.y; Z[2]=v0.z; Z[3]=v0.w; Z[4]=v1.x; Z[5]=v1.y; Z[6]=v1.z; Z[7]=v1.w;
            p = (const float4*)(ab + n0);
            v0 = p[0]; v1 = p[1];
            W[0]=v0.x; W[1]=v0.y; W[2]=v0.z; W[3]=v0.w; W[4]=v1.x; W[5]=v1.y; W[6]=v1.z; W[7]=v1.w;
        }
        int myrep = 0x7FFFFFFF;
        #pragma unroll
        for (int j = 0; j < 8; j++) {
            float a = W[j];
            float w = BRANCH ? __fsub_rn(1.0f, a) : a;   // exact: a in {0,1}
            W[j] = w;
            X[j] = __fmul_rn(w, X[j]);
            Y[j] = __fmul_rn(w, Y[j]);
            Z[j] = __fmul_rn(w, Z[j]);
            if (w == 0.0f && (n0 + j) < myrep) myrep = n0 + j;
        }
        __syncthreads();
        if (myrep != 0x7FFFFFFF) atomicMin(&srep, myrep);
        __syncthreads();
        rep = srep;

        unsigned cnt = 0, kmask = 0;
        #pragma unroll
        for (int j = 0; j < 8; j++) {
            bool kp = (W[j] != 0.0f) || ((n0 + j) == rep);
            if (kp) { kmask |= (1u << j); cnt++; }
        }
        unsigned inc = cnt;
        #pragma unroll
        for (int off = 1; off < 32; off <<= 1) {
            unsigned v = __shfl_up_sync(0xffffffffu, inc, off);
            if (lane >= off) inc += v;
        }
        if (lane == 31) sscan[wid] = inc;
        __syncthreads();
        if (wid == 0) {
            unsigned v = sscan[lane];
            #pragma unroll
            for (int off = 1; off < 32; off <<= 1) {
                unsigned u = __shfl_up_sync(0xffffffffu, v, off);
                if (lane >= off) v += u;
            }
            sscan[lane] = v;
        }
        __syncthreads();
        m = (int)sscan[31];
        int o = (int)((wid ? sscan[wid - 1] : 0u) + (inc - cnt));
        #pragma unroll
        for (int j = 0; j < 8; j++) {
            if ((kmask >> j) & 1u) {
                sx[o] = X[j]; sy[o] = Y[j]; sz[o] = Z[j]; sid[o] = n0 + j;
                o++;
            }
        }
        for (int s2 = t; s2 < 4097; s2 += 1024) smd[s2] = 1e10f;
        __syncthreads();

        #pragma unroll
        for (int j = 0; j < 4; j++) {
            int sl = t + j * 1024;
            bool v = sl < m;
            px[j] = v ? sx[sl] : 0.0f;
            py[j] = v ? sy[sl] : 0.0f;
            pz[j] = v ? sz[sl] : 0.0f;
            md[j] = v ? 1e10f : 0.0f;
        }
        cur = 0;

        if (k1 < K) {
            for (int sl = t; sl < m; sl += 1024) {
                g_cx[b][sl] = sx[sl]; g_cy[b][sl] = sy[sl];
                g_cz[b][sl] = sz[sl]; g_cid[b][sl] = sid[sl];
            }
            if (t == 0) { g_state[b][0] = m; g_state[b][1] = rep; }
        }
    } else {
        m   = g_state[b][0];
        rep = g_state[b][1];
        cur = g_state[b][2];
        for (int sl = t; sl < m; sl += 1024) {
            sx[sl] = g_cx[b][sl]; sy[sl] = g_cy[b][sl];
            sz[sl] = g_cz[b][sl]; sid[sl] = g_cid[b][sl];
        }
        #pragma unroll
        for (int j = 0; j < 4; j++) md[j] = g_cmd[b][t + j * 1024];
        for (int sl = 4096 + t; sl < m; sl += 1024) smd[sl - 4096] = g_cmd[b][sl];
        __syncthreads();
        #pragma unroll
        for (int j = 0; j < 4; j++) {
            int sl = t + j * 1024;
            px[j] = 0.0f; py[j] = 0.0f; pz[j] = 0.0f;
            if (sl < m) { px[j] = sx[sl]; py[j] = sy[sl]; pz[j] = sz[sl]; }
        }
    }

    float* out_xyz  = out;                                           // [B,3,512]
    float* out_attn = out + BATCH * 3 * S_ALL + BATCH * 128 * S_ALL; // [B,1,512]

    for (int k = k0; k < k1; k++) {
        float bx = sx[cur], by = sy[cur], bz = sz[cur];
        if (t == 0) {
            int s = s_off + k;
            out_xyz[(b * 3 + 0) * S_ALL + s] = bx;
            out_xyz[(b * 3 + 1) * S_ALL + s] = by;
            out_xyz[(b * 3 + 2) * S_ALL + s] = bz;
            g_new_xyz[(b * S_ALL + s) * 3 + 0] = bx;
            g_new_xyz[(b * S_ALL + s) * 3 + 1] = by;
            g_new_xyz[(b * S_ALL + s) * 3 + 2] = bz;
            int orig = sid[cur];
            float att = BRANCH ? ((orig == rep) ? 1.0f : 0.0f)
                               : ((orig == rep) ? 0.0f : 1.0f);
            out_attn[b * S_ALL + s] = att;
        }
        if (k == K - 1) break;

        unsigned long long bk = 0ull;
        #pragma unroll
        for (int j = 0; j < 4; j++) {
            float dx = __fsub_rn(px[j], bx);
            float dy = __fsub_rn(py[j], by);
            float dz = __fsub_rn(pz[j], bz);
            float d2 = __fadd_rn(__fadd_rn(__fmul_rn(dx, dx), __fmul_rn(dy, dy)),
                                 __fmul_rn(dz, dz));
            float mn = fminf(md[j], d2);
            md[j] = mn;
            int sl = t + j * 1024;
            unsigned long long key =
                ((unsigned long long)__float_as_uint(mn) << 32) |
                (unsigned long long)(0xFFFFFFFFu - (unsigned)sl);
            if (key > bk) bk = key;
        }
        for (int sl = 4096 + t; sl < m; sl += 1024) {
            float dx = __fsub_rn(sx[sl], bx);
            float dy = __fsub_rn(sy[sl], by);
            float dz = __fsub_rn(sz[sl], bz);
            float d2 = __fadd_rn(__fadd_rn(__fmul_rn(dx, dx), __fmul_rn(dy, dy)),
                                 __fmul_rn(dz, dz));
            float mn = fminf(smd[sl - 4096], d2);
            smd[sl - 4096] = mn;
            unsigned long long key =
                ((unsigned long long)__float_as_uint(mn) << 32) |
                (unsigned long long)(0xFFFFFFFFu - (unsigned)sl);
            if (key > bk) bk = key;
        }
        unsigned vb   = (unsigned)(bk >> 32);
        unsigned vmax = __reduce_max_sync(0xffffffffu, vb);
        unsigned lo   = (vb == vmax) ? (unsigned)bk : 0u;
        unsigned lmax = __reduce_max_sync(0xffffffffu, lo);
        if (lane == 0) sred[k & 1][wid] = ((unsigned long long)vmax << 32) | lmax;
        __syncthreads();
        unsigned long long e = sred[k & 1][lane];
        vb   = (unsigned)(e >> 32);
        vmax = __reduce_max_sync(0xffffffffu, vb);
        lo   = (vb == vmax) ? (unsigned)e : 0u;
        lmax = __reduce_max_sync(0xffffffffu, lo);
        cur  = (int)(0xFFFFFFFFu - lmax);
    }

    if (k1 < K) {
        #pragma unroll
        for (int j = 0; j < 4; j++) g_cmd[b][t + j * 1024] = md[j];
        for (int sl = 4096 + t; sl < m; sl += 1024) g_cmd[b][sl] = smd[sl - 4096];
        if (t == 0) g_state[b][2] = cur;
    }
}

// ================= group + MLP + maxpool: 128-thread CTA per (b,s) =================
// Ball query: barrier-free bitmask pass (64 ballots/warp into 256-word mask),
// one block-scan, rank-based expansion of the first 64 set bits (index order ==
// reference order). MLP identical to R12 (output-pair f32x2, full unroll).
template <int S_BASE, int NS>
__global__ __launch_bounds__(128, 8) void group_mlp_kernel(
    const float* __restrict__ xyz,
    const float* __restrict__ b0, const float* __restrict__ b1,
    const float* __restrict__ b2,
    float* __restrict__ out)
{
    __shared__ __align__(16) float sfeat[68 * 64];   // [c][k]; rows 0..63 reused for h1, h2
    __shared__ unsigned smask[256];                  // neighbor bitmask, 8192 bits
    __shared__ int sidx[64];
    __shared__ int swsum[4];

    int t = threadIdx.x;
    int wid = t >> 5, lane = t & 31;

    int bs = blockIdx.x;
    int b = bs / NS;
    int s = S_BASE + (bs - b * NS);

    const float* xb = xyz + (size_t)b * 3 * NPTS;
    float qx = g_new_xyz[(b * S_ALL + s) * 3 + 0];
    float qy = g_new_xyz[(b * S_ALL + s) * 3 + 1];
    float qz = g_new_xyz[(b * S_ALL + s) * 3 + 2];
    const float R2 = (float)(0.4 * 0.4);

    if (t < 64) { sidx[t] = -1; sfeat[67 * 64 + t] = 0.0f; }

    // ---- phase 1: per-warp ballots over a 2048-point segment (no block barriers) ----
    {
        int nb = wid * 2048 + lane;
        #pragma unroll 8
        for (int i = 0; i < 64; i++) {
            int n = nb + i * 32;
            float dx = __fsub_rn(qx, xb[n]);
            float dy = __fsub_rn(qy, xb[NPTS + n]);
            float dz = __fsub_rn(qz, xb[2 * NPTS + n]);
            float d2 = __fadd_rn(__fadd_rn(__fmul_rn(dx, dx), __fmul_rn(dy, dy)),
                                 __fmul_rn(dz, dz));
            unsigned ball = __ballot_sync(0xffffffffu, d2 < R2);
            if (lane == 0) smask[wid * 64 + i] = ball;
        }
    }
    __syncthreads();

    // ---- phase 2: block scan over 256 popcounts (2 words per thread) ----
    {
        unsigned m0 = smask[2 * t], m1 = smask[2 * t + 1];
        int p0 = __popc(m0), p1 = __popc(m1);
        int sum = p0 + p1;
        int incl = sum;
        #pragma unroll
        for (int off = 1; off < 32; off <<= 1) {
            int v = __shfl_up_sync(0xffffffffu, incl, off);
            if (lane >= off) incl += v;
        }
        if (lane == 31) swsum[wid] = incl;
        __syncthreads();
        int base = 0;
        #pragma unroll
        for (int w = 0; w < 4; w++) {
            int v = swsum[w];
            if (w < wid) base += v;
        }
        int excl = base + incl - sum;

        // ---- phase 3: expand first-64 set bits by global rank ----
        int r0 = excl;
        if (r0 < 64 && m0) {
            unsigned mm = m0;
            int r = r0;
            while (mm && r < 64) {
                int bit = __ffs(mm) - 1;
                mm &= mm - 1;
                sidx[r++] = 2 * t * 32 + bit;
            }
        }
        int r1 = excl + p0;
        if (r1 < 64 && m1) {
            unsigned mm = m1;
            int r = r1;
            while (mm && r < 64) {
                int bit = __ffs(mm) - 1;
                mm &= mm - 1;
                sidx[r++] = (2 * t + 1) * 32 + bit;
            }
        }
    }
    __syncthreads();

    // ---- feat [68][64] ----
    if (t < 64) {
        int idx = sidx[t];
        float gx = (idx >= 0) ? xb[idx] : 0.0f;
        float gy = (idx >= 0) ? xb[NPTS + idx] : 0.0f;
        float gz = (idx >= 0) ? xb[2 * NPTS + idx] : 0.0f;
        sfeat[0 * 64 + t] = __fsub_rn(gx, qx);
        sfeat[1 * 64 + t] = __fsub_rn(gy, qy);
        sfeat[2 * 64 + t] = __fsub_rn(gz, qz);
    }
    {
        int kk = t & 63, fq = t >> 6;            // 2 threads per sample row, 8 float4 each
        int idx = sidx[kk];
        int gi = (idx >= 0) ? idx : (NPTS - 1);
        const float4* row = (const float4*)(g_pts_t + ((size_t)b * NPTS + gi) * DF);
        #pragma unroll
        for (int f2 = 0; f2 < 8; f2++) {
            int f = fq * 8 + f2;
            float4 v = row[f];
            sfeat[(3 + 4 * f + 0) * 64 + kk] = v.x;
            sfeat[(3 + 4 * f + 1) * 64 + kk] = v.y;
            sfeat[(3 + 4 * f + 2) * 64 + kk] = v.z;
            sfeat[(3 + 4 * f + 3) * 64 + kk] = v.w;
        }
    }
    __syncthreads();

    int og = t >> 4;              // 0..7  (8 output rows each -> 4 output PAIRS)
    int kb = (t & 15) * 4;        // 0..60 (4 samples)
    const float* fp = sfeat + kb;

    ull acc[4][4];                // [output pair][sample]

    // ---- layer1: 68(pad) -> 64, relu ----
    {
        const float* w0p = g_w0t + og * 8;    // column offset; row stride 64
        #pragma unroll
        for (int p = 0; p < 4; p++) {
            ull bv = __ldg((const ull*)(b0 + og * 8 + 2 * p));
            acc[p][0] = bv; acc[p][1] = bv; acc[p][2] = bv; acc[p][3] = bv;
        }
        #pragma unroll
        for (int c = 0; c < 68; c++) {
            float4 f = *(const float4*)(fp + c * 64);
            ull fb0, fb1, fb2, fb3;
            PACK2(fb0, f.x); PACK2(fb1, f.y); PACK2(fb2, f.z); PACK2(fb3, f.w);
            ulonglong2 wA = __ldg((const ulonglong2*)(w0p + c * 64));      // pairs (o0,o1),(o2,o3)
            ulonglong2 wB = __ldg((const ulonglong2*)(w0p + c * 64 + 4));  // pairs (o4,o5),(o6,o7)
            FMA2(acc[0][0], wA.x, fb0, acc[0][0]); FMA2(acc[0][1], wA.x, fb1, acc[0][1]);
            FMA2(acc[0][2], wA.x, fb2, acc[0][2]); FMA2(acc[0][3], wA.x, fb3, acc[0][3]);
            FMA2(acc[1][0], wA.y, fb0, acc[1][0]); FMA2(acc[1][1], wA.y, fb1, acc[1][1]);
            FMA2(acc[1][2], wA.y, fb2, acc[1][2]); FMA2(acc[1][3], wA.y, fb3, acc[1][3]);
            FMA2(acc[2][0], wB.x, fb0, acc[2][0]); FMA2(acc[2][1], wB.x, fb1, acc[2][1]);
            FMA2(acc[2][2], wB.x, fb2, acc[2][2]); FMA2(acc[2][3], wB.x, fb3, acc[2][3]);
            FMA2(acc[3][0], wB.y, fb0, acc[3][0]); FMA2(acc[3][1], wB.y, fb1, acc[3][1]);
            FMA2(acc[3][2], wB.y, fb2, acc[3][2]); FMA2(acc[3][3], wB.y, fb3, acc[3][3]);
        }
        __syncthreads();   // all layer-1 reads of sfeat complete
        #pragma unroll
        for (int p = 0; p < 4; p++) {
            float e0, o0, e1, o1, e2, o2, e3, o3;
            UNPACK2(e0, o0, acc[p][0]); UNPACK2(e1, o1, acc[p][1]);
            UNPACK2(e2, o2, acc[p][2]); UNPACK2(e3, o3, acc[p][3]);
            float4 re = { fmaxf(e0,0.f), fmaxf(e1,0.f), fmaxf(e2,0.f), fmaxf(e3,0.f) };
            float4 ro = { fmaxf(o0,0.f), fmaxf(o1,0.f), fmaxf(o2,0.f), fmaxf(o3,0.f) };
            *(float4*)(sfeat + (og * 8 + 2 * p + 0) * 64 + kb) = re;
            *(float4*)(sfeat + (og * 8 + 2 * p + 1) * 64 + kb) = ro;
        }
    }
    __syncthreads();

    // ---- layer2: 64 -> 64, relu ----
    {
        const float* w1p = g_w1t + og * 8;
        #pragma unroll
        for (int p = 0; p < 4; p++) {
            ull bv = __ldg((const ull*)(b1 + og * 8 + 2 * p));
            acc[p][0] = bv; acc[p][1] = bv; acc[p][2] = bv; acc[p][3] = bv;
        }
        #pragma unroll
        for (int c = 0; c < 64; c++) {
            float4 f = *(const float4*)(fp + c * 64);
            ull fb0, fb1, fb2, fb3;
            PACK2(fb0, f.x); PACK2(fb1, f.y); PACK2(fb2, f.z); PACK2(fb3, f.w);
            ulonglong2 wA = __ldg((const ulonglong2*)(w1p + c * 64));
            ulonglong2 wB = __ldg((const ulonglong2*)(w1p + c * 64 + 4));
            FMA2(acc[0][0], wA.x, fb0, acc[0][0]); FMA2(acc[0][1], wA.x, fb1, acc[0][1]);
            FMA2(acc[0][2], wA.x, fb2, acc[0][2]); FMA2(acc[0][3], wA.x, fb3, acc[0][3]);
            FMA2(acc[1][0], wA.y, fb0, acc[1][0]); FMA2(acc[1][1], wA.y, fb1, acc[1][1]);
            FMA2(acc[1][2], wA.y, fb2, acc[1][2]); FMA2(acc[1][3], wA.y, fb3, acc[1][3]);
            FMA2(acc[2][0], wB.x, fb0, acc[2][0]); FMA2(acc[2][1], wB.x, fb1, acc[2][1]);
            FMA2(acc[2][2], wB.x, fb2, acc[2][2]); FMA2(acc[2][3], wB.x, fb3, acc[2][3]);
            FMA2(acc[3][0], wB.y, fb0, acc[3][0]); FMA2(acc[3][1], wB.y, fb1, acc[3][1]);
            FMA2(acc[3][2], wB.y, fb2, acc[3][2]); FMA2(acc[3][3], wB.y, fb3, acc[3][3]);
        }
        __syncthreads();   // all layer-2 reads complete before overwrite
        #pragma unroll
        for (int p = 0; p < 4; p++) {
            float e0, o0, e1, o1, e2, o2, e3, o3;
            UNPACK2(e0, o0, acc[p][0]); UNPACK2(e1, o1, acc[p][1]);
            UNPACK2(e2, o2, acc[p][2]); UNPACK2(e3, o3, acc[p][3]);
            float4 re = { fmaxf(e0,0.f), fmaxf(e1,0.f), fmaxf(e2,0.f), fmaxf(e3,0.f) };
            float4 ro = { fmaxf(o0,0.f), fmaxf(o1,0.f), fmaxf(o2,0.f), fmaxf(o3,0.f) };
            *(float4*)(sfeat + (og * 8 + 2 * p + 0) * 64 + kb) = re;
            *(float4*)(sfeat + (og * 8 + 2 * p + 1) * 64 + kb) = ro;
        }
    }
    __syncthreads();

    // ---- layer3: 64 -> 128, relu + maxpool; two passes of 64 outputs ----
    {
        float* out_points = out + BATCH * 3 * S_ALL;   // [B,128,512]
        #pragma unroll 1
        for (int h = 0; h < 2; h++) {
            const float* w2p = g_w2t + h * 64 + og * 8;   // row stride 128
            #pragma unroll
            for (int p = 0; p < 4; p++) {
                ull bv = __ldg((const ull*)(b2 + h * 64 + og * 8 + 2 * p));
                acc[p][0] = bv; acc[p][1] = bv; acc[p][2] = bv; acc[p][3] = bv;
            }
            #pragma unroll
            for (int c = 0; c < 64; c++) {
                float4 f = *(const float4*)(fp + c * 64);
                ull fb0, fb1, fb2, fb3;
                PACK2(fb0, f.x); PACK2(fb1, f.y); PACK2(fb2, f.z); PACK2(fb3, f.w);
                ulonglong2 wA = __ldg((const ulonglong2*)(w2p + c * 128));
                ulonglong2 wB = __ldg((const ulonglong2*)(w2p + c * 128 + 4));
                FMA2(acc[0][0], wA.x, fb0, acc[0][0]); FMA2(acc[0][1], wA.x, fb1, acc[0][1]);
                FMA2(acc[0][2], wA.x, fb2, acc[0][2]); FMA2(acc[0][3], wA.x, fb3, acc[0][3]);
                FMA2(acc[1][0], wA.y, fb0, acc[1][0]); FMA2(acc[1][1], wA.y, fb1, acc[1][1]);
                FMA2(acc[1][2], wA.y, fb2, acc[1][2]); FMA2(acc[1][3], wA.y, fb3, acc[1][3]);
                FMA2(acc[2][0], wB.x, fb0, acc[2][0]); FMA2(acc[2][1], wB.x, fb1, acc[2][1]);
                FMA2(acc[2][2], wB.x, fb2, acc[2][2]); FMA2(acc[2][3], wB.x, fb3, acc[2][3]);
                FMA2(acc[3][0], wB.y, fb0, acc[3][0]); FMA2(acc[3][1], wB.y, fb1, acc[3][1]);
                FMA2(acc[3][2], wB.y, fb2, acc[3][2]); FMA2(acc[3][3], wB.y, fb3, acc[3][3]);
            }
            #pragma unroll
            for (int p = 0; p < 4; p++) {
                float e0, o0, e1, o1, e2, o2, e3, o3;
                UNPACK2(e0, o0, acc[p][0]); UNPACK2(e1, o1, acc[p][1]);
                UNPACK2(e2, o2, acc[p][2]); UNPACK2(e3, o3, acc[p][3]);
                float me = fmaxf(fmaxf(e0, e1), fmaxf(e2, e3));
                float mo = fmaxf(fmaxf(o0, o1), fmaxf(o2, o3));
                #pragma unroll
                for (int off = 1; off < 16; off <<= 1) {
                    me = fmaxf(me, __shfl_xor_sync(0xffffffffu, me, off));
                    mo = fmaxf(mo, __shfl_xor_sync(0xffffffffu, mo, off));
                }
                if ((t & 15) == 0) {
                    size_t base = (size_t)b * 128 + h * 64 + og * 8 + 2 * p;
                    out_points[(base + 0) * S_ALL + s] = fmaxf(me, 0.0f);
                    out_points[(base + 1) * S_ALL + s] = fmaxf(mo, 0.0f);
                }
            }
        }
    }
}

extern "C" void kernel_launch(void* const* d_in, const int* in_sizes, int n_in,
                              void* d_out, int out_size) {
    const float* xyz       = (const float*)d_in[0];
    const float* points    = (const float*)d_in[1];
    const float* attention = (const float*)d_in[2];
    const float* w0 = (const float*)d_in[3];
    const float* b0 = (const float*)d_in[4];
    const float* w1 = (const float*)d_in[5];
    const float* b1 = (const float*)d_in[6];
    const float* w2 = (const float*)d_in[7];
    const float* b2 = (const float*)d_in[8];
    float* out = (float*)d_out;

    static cudaStream_t sA = nullptr, sB = nullptr, sD = nullptr;
    static cudaEvent_t eFork = nullptr, eT = nullptr, eA = nullptr, eD = nullptr;
    static cudaEvent_t eN[4] = {nullptr, nullptr, nullptr, nullptr};
    if (sA == nullptr) {
        cudaStreamCreateWithFlags(&sA, cudaStreamNonBlocking);
        cudaStreamCreateWithFlags(&sB, cudaStreamNonBlocking);
        cudaStreamCreateWithFlags(&sD, cudaStreamNonBlocking);
        cudaEventCreateWithFlags(&eFork, cudaEventDisableTiming);
        cudaEventCreateWithFlags(&eT,    cudaEventDisableTiming);
        cudaEventCreateWithFlags(&eA,    cudaEventDisableTiming);
        cudaEventCreateWithFlags(&eD,    cudaEventDisableTiming);
        for (int i = 0; i < 4; i++) cudaEventCreateWithFlags(&eN[i], cudaEventDisableTiming);
    }

    const int fps_smem = 8193 * 16 + 4097 * 4;
    cudaFuncSetAttribute(fps_kernel<0>, cudaFuncAttributeMaxDynamicSharedMemorySize, fps_smem);
    cudaFuncSetAttribute(fps_kernel<1>, cudaFuncAttributeMaxDynamicSharedMemorySize, fps_smem);

    prep_w_kernel<<<32, 256>>>(w0, w1, w2);   // 8192 threads cover 64*128

    cudaEventRecord(eFork, 0);
    cudaStreamWaitEvent(sA, eFork, 0);
    cudaStreamWaitEvent(sB, eFork, 0);
    cudaStreamWaitEvent(sD, eFork, 0);

    // stream A: transpose -> FPS(attn) -> group(attn sites 0..127)
    transpose_kernel<<<dim3(256, 2, 8), dim3(32, 32), 0, sA>>>(points);
    cudaEventRecord(eT, sA);
    fps_kernel<0><<<BATCH, 1024, fps_smem, sA>>>(xyz, attention, out, 0, K_ATTN);
    group_mlp_kernel<0, 128><<<BATCH * 128, 128, 0, sA>>>(xyz, b0, b1, b2, out);
    cudaEventRecord(eA, sA);

    // stream B: FPS(none) in 4 chunks of 96 iterations
    fps_kernel<1><<<BATCH, 1024, fps_smem, sB>>>(xyz, attention, out, 0, 96);
    cudaEventRecord(eN[0], sB);
    fps_kernel<1><<<BATCH, 1024, fps_smem, sB>>>(xyz, attention, out, 96, 192);
    cudaEventRecord(eN[1], sB);
    fps_kernel<1><<<BATCH, 1024, fps_smem, sB>>>(xyz, attention, out, 192, 288);
    cudaEventRecord(eN[2], sB);
    fps_kernel<1><<<BATCH, 1024, fps_smem, sB>>>(xyz, attention, out, 288, 384);
    cudaEventRecord(eN[3], sB);

    // stream D: group(none) in 4 site-chunks, gated on FPS chunks (+transpose)
    cudaStreamWaitEvent(sD, eT, 0);
    cudaStreamWaitEvent(sD, eN[0], 0);
    group_mlp_kernel<128, 96><<<BATCH * 96, 128, 0, sD>>>(xyz, b0, b1, b2, out);
    cudaStreamWaitEvent(sD, eN[1], 0);
    group_mlp_kernel<224, 96><<<BATCH * 96, 128, 0, sD>>>(xyz, b0, b1, b2, out);
    cudaStreamWaitEvent(sD, eN[2], 0);
    group_mlp_kernel<320, 96><<<BATCH * 96, 128, 0, sD>>>(xyz, b0, b1, b2, out);
    cudaStreamWaitEvent(sD, eN[3], 0);
    group_mlp_kernel<416, 96><<<BATCH * 96, 128, 0, sD>>>(xyz, b0, b1, b2, out);
    cudaEventRecord(eD, sD);

    cudaStreamWaitEvent(0, eA, 0);
    cudaStreamWaitEvent(0, eD, 0);
}